// round 1
// baseline (speedup 1.0000x reference)
#include <cuda_runtime.h>
#include <cstdint>

#define BB    16
#define LL    512
#define DIMD  256
#define DIN   512
#define DSTATE 16
#define DTRANK 16
#define NTOK  (BB*LL)   // 8192
#define DBCN  (DTRANK + 2*DSTATE)  // 48

// ------------- scratch (device globals: allocation-free) -------------
__device__ float g_h  [NTOK * DIMD];        //  8 MB
__device__ float g_xz [NTOK * 2 * DIN];     // 32 MB
__device__ float g_xc [NTOK * DIN];         // 16 MB
__device__ float g_dbc[NTOK * DBCN];        // 1.5 MB
__device__ float g_dt [NTOK * DIN];         // 16 MB
__device__ float g_y  [NTOK * DIN];         // 16 MB

// ------------------------- LayerNorm -------------------------
// one warp per row of 256; 8 rows per 256-thread CTA
__global__ void ln_kernel(const float* __restrict__ x,
                          const float* __restrict__ w,
                          const float* __restrict__ b,
                          float* __restrict__ h)
{
    int row  = blockIdx.x * 8 + (threadIdx.x >> 5);
    int lane = threadIdx.x & 31;
    const float* xr = x + (size_t)row * DIMD;
    float4 v0 = *(const float4*)(xr + lane * 8);
    float4 v1 = *(const float4*)(xr + lane * 8 + 4);
    float s  = v0.x+v0.y+v0.z+v0.w + v1.x+v1.y+v1.z+v1.w;
    float q  = v0.x*v0.x+v0.y*v0.y+v0.z*v0.z+v0.w*v0.w
             + v1.x*v1.x+v1.y*v1.y+v1.z*v1.z+v1.w*v1.w;
    #pragma unroll
    for (int o = 16; o; o >>= 1) {
        s += __shfl_xor_sync(0xffffffffu, s, o);
        q += __shfl_xor_sync(0xffffffffu, q, o);
    }
    float mu  = s * (1.f/DIMD);
    float var = q * (1.f/DIMD) - mu*mu;
    float rs  = rsqrtf(var + 1e-5f);
    float* hr = h + (size_t)row * DIMD;
    int c = lane * 8;
    float4 w0 = *(const float4*)(w + c),  w1 = *(const float4*)(w + c + 4);
    float4 b0 = *(const float4*)(b + c),  b1 = *(const float4*)(b + c + 4);
    float4 o0, o1;
    o0.x = (v0.x-mu)*rs*w0.x + b0.x;  o0.y = (v0.y-mu)*rs*w0.y + b0.y;
    o0.z = (v0.z-mu)*rs*w0.z + b0.z;  o0.w = (v0.w-mu)*rs*w0.w + b0.w;
    o1.x = (v1.x-mu)*rs*w1.x + b1.x;  o1.y = (v1.y-mu)*rs*w1.y + b1.y;
    o1.z = (v1.z-mu)*rs*w1.z + b1.z;  o1.w = (v1.w-mu)*rs*w1.w + b1.w;
    *(float4*)(hr + c)     = o0;
    *(float4*)(hr + c + 4) = o1;
}

// ------------------------- GEMM: C[M,N] = A[M,K] @ Bw[N,K]^T -------------------------
// MODE 0: plain   MODE 1: +bias[n]   MODE 2: C += acc (residual, C preloaded)
template<int MODE>
__global__ __launch_bounds__(256, 2)
void gemm128(const float* __restrict__ A, const float* __restrict__ Bw,
             const float* __restrict__ bias,
             float* __restrict__ C, int M, int N, int K)
{
    __shared__ float As[8][132];
    __shared__ float Bs[8][132];
    const int tid  = threadIdx.x;
    const int row0 = blockIdx.y * 128;
    const int col0 = blockIdx.x * 128;
    const int lr   = tid >> 1;          // 0..127
    const int lc   = (tid & 1) << 2;    // 0 or 4
    const int tx   = tid & 15;
    const int ty   = tid >> 4;

    float acc[8][8];
    #pragma unroll
    for (int i = 0; i < 8; i++)
        #pragma unroll
        for (int j = 0; j < 8; j++) acc[i][j] = 0.f;

    const float* Aptr = A  + (size_t)(row0 + lr) * K + lc;
    const float* Bptr = Bw + (size_t)(col0 + lr) * K + lc;
    const bool bvalid = (col0 + lr) < N;

    for (int k0 = 0; k0 < K; k0 += 8) {
        float4 av = *(const float4*)(Aptr + k0);
        float4 bv = make_float4(0.f, 0.f, 0.f, 0.f);
        if (bvalid) bv = *(const float4*)(Bptr + k0);
        __syncthreads();
        As[lc+0][lr] = av.x; As[lc+1][lr] = av.y; As[lc+2][lr] = av.z; As[lc+3][lr] = av.w;
        Bs[lc+0][lr] = bv.x; Bs[lc+1][lr] = bv.y; Bs[lc+2][lr] = bv.z; Bs[lc+3][lr] = bv.w;
        __syncthreads();
        #pragma unroll
        for (int k = 0; k < 8; k++) {
            float4 a0 = *(const float4*)&As[k][ty<<2];
            float4 a1 = *(const float4*)&As[k][(ty<<2) + 64];
            float4 b0 = *(const float4*)&Bs[k][tx<<2];
            float4 b1 = *(const float4*)&Bs[k][(tx<<2) + 64];
            float a[8] = {a0.x,a0.y,a0.z,a0.w,a1.x,a1.y,a1.z,a1.w};
            float b[8] = {b0.x,b0.y,b0.z,b0.w,b1.x,b1.y,b1.z,b1.w};
            #pragma unroll
            for (int i = 0; i < 8; i++)
                #pragma unroll
                for (int j = 0; j < 8; j++) acc[i][j] += a[i] * b[j];
        }
    }

    #pragma unroll
    for (int i = 0; i < 8; i++) {
        int m = row0 + ((i < 4) ? (ty<<2) + i : 60 + (ty<<2) + i);
        #pragma unroll
        for (int j = 0; j < 8; j++) {
            int n = col0 + ((j < 4) ? (tx<<2) + j : 60 + (tx<<2) + j);
            if (n < N) {
                float v = acc[i][j];
                if (MODE == 1) v += bias[n];
                float* cp = &C[(size_t)m * N + n];
                if (MODE == 2) v += *cp;
                *cp = v;
            }
        }
    }
}

// ------------------------- depthwise causal conv (k=4) + SiLU -------------------------
__global__ void conv_kernel(const float* __restrict__ xz,   // [NTOK, 1024], xin = cols 0..511
                            const float* __restrict__ cw,   // [512,4]
                            const float* __restrict__ cb,   // [512]
                            float* __restrict__ xc)         // [NTOK, 512]
{
    int idx = blockIdx.x * blockDim.x + threadIdx.x;
    if (idx >= NTOK * DIN) return;
    int d   = idx & (DIN - 1);
    int tok = idx >> 9;
    int l   = tok & (LL - 1);
    float s = cb[d];
    #pragma unroll
    for (int k = 0; k < 4; k++) {
        int ll = l - 3 + k;
        if (ll >= 0)
            s += cw[d*4 + k] * xz[(size_t)(tok - 3 + k) * 1024 + d];
    }
    float sg = 1.f / (1.f + __expf(-s));
    xc[idx] = s * sg;
}

// ------------------------- dt projection + softplus -------------------------
__global__ void dtproj_kernel(const float* __restrict__ dbc,  // [NTOK,48]
                              const float* __restrict__ dtw,  // [512,16]
                              const float* __restrict__ dtb,  // [512]
                              float* __restrict__ dt)         // [NTOK,512]
{
    int tok = blockIdx.x;
    int d   = threadIdx.x;
    const float* r = dbc + (size_t)tok * DBCN;
    float rv[16];
    #pragma unroll
    for (int i = 0; i < 16; i++) rv[i] = r[i];
    const float4* w4 = (const float4*)(dtw + d * 16);
    float4 w0 = w4[0], w1 = w4[1], w2 = w4[2], w3 = w4[3];
    float s = dtb[d];
    s += w0.x*rv[0]  + w0.y*rv[1]  + w0.z*rv[2]  + w0.w*rv[3];
    s += w1.x*rv[4]  + w1.y*rv[5]  + w1.z*rv[6]  + w1.w*rv[7];
    s += w2.x*rv[8]  + w2.y*rv[9]  + w2.z*rv[10] + w2.w*rv[11];
    s += w3.x*rv[12] + w3.y*rv[13] + w3.z*rv[14] + w3.w*rv[15];
    dt[(size_t)tok * DIN + d] = (s > 20.f) ? s : log1pf(__expf(s));
}

// ------------------------- selective scan (+ u*D, * silu(z)) -------------------------
// grid (8 channel-chunks, 16 batches), 128 threads.
// Each warp handles 16 channels; lanes 0-15 own states 0-7, lanes 16-31 own states 8-15
// of the SAME 16 channels; y combined via shfl_xor(16).
__global__ __launch_bounds__(128)
void scan_kernel(const float* __restrict__ u,     // g_xc [NTOK,512]
                 const float* __restrict__ dt,    // [NTOK,512]
                 const float* __restrict__ dbc,   // [NTOK,48] (B at col 16, C at 32)
                 const float* __restrict__ xz,    // [NTOK,1024] (z at col 512)
                 const float* __restrict__ A_log, // [512,16]
                 const float* __restrict__ Dp,    // [512]
                 float* __restrict__ y)           // [NTOK,512]
{
    const int tid   = threadIdx.x;
    const int lane  = tid & 31;
    const int warp  = tid >> 5;
    const int half  = lane >> 4;                 // which 8-state half
    const int d     = blockIdx.x * 64 + warp * 16 + (lane & 15);
    const int bbase = blockIdx.y * LL;

    float A[8];
    #pragma unroll
    for (int i = 0; i < 8; i++)
        A[i] = -__expf(A_log[d * DSTATE + half * 8 + i]);
    const float Dd = Dp[d];

    float h[8];
    #pragma unroll
    for (int i = 0; i < 8; i++) h[i] = 0.f;

    __shared__ float sB[8][16];
    __shared__ float sC[8][16];

    for (int t0 = 0; t0 < LL; t0 += 8) {
        __syncthreads();
        #pragma unroll
        for (int i = tid; i < 256; i += 128) {
            int step = i >> 5, idx = i & 31;
            float v = dbc[(size_t)(bbase + t0 + step) * DBCN + DTRANK + idx];
            if (idx < 16) sB[step][idx] = v;
            else          sC[step][idx - 16] = v;
        }
        __syncthreads();
        #pragma unroll
        for (int s = 0; s < 8; s++) {
            int tok = bbase + t0 + s;
            float dtv = dt[(size_t)tok * DIN + d];
            float uv  = u [(size_t)tok * DIN + d];
            float du  = dtv * uv;
            float yp  = 0.f;
            #pragma unroll
            for (int i = 0; i < 8; i++) {
                float dA = __expf(dtv * A[i]);
                float Bv = sB[s][half * 8 + i];
                h[i] = dA * h[i] + du * Bv;
                yp += h[i] * sC[s][half * 8 + i];
            }
            float ytot = yp + __shfl_xor_sync(0xffffffffu, yp, 16);
            if (half == 0) {
                float zv = xz[(size_t)tok * 1024 + DIN + d];
                float sz = zv / (1.f + __expf(-zv));
                y[(size_t)tok * DIN + d] = (ytot + uv * Dd) * sz;
            }
        }
    }
}

// ------------------------- host -------------------------
extern "C" void kernel_launch(void* const* d_in, const int* in_sizes, int n_in,
                              void* d_out, int out_size)
{
    const float* x    = (const float*)d_in[0];
    const float* lnw  = (const float*)d_in[1];
    const float* lnb  = (const float*)d_in[2];
    const float* inw  = (const float*)d_in[3];
    const float* inb  = (const float*)d_in[4];
    const float* cw   = (const float*)d_in[5];
    const float* cb   = (const float*)d_in[6];
    const float* xpw  = (const float*)d_in[7];
    const float* dtw  = (const float*)d_in[8];
    const float* dtb  = (const float*)d_in[9];
    const float* Alog = (const float*)d_in[10];
    const float* Dp   = (const float*)d_in[11];
    const float* ow   = (const float*)d_in[12];
    float* out = (float*)d_out;

    float *ph, *pxz, *pxc, *pdbc, *pdt, *py;
    cudaGetSymbolAddress((void**)&ph,   g_h);
    cudaGetSymbolAddress((void**)&pxz,  g_xz);
    cudaGetSymbolAddress((void**)&pxc,  g_xc);
    cudaGetSymbolAddress((void**)&pdbc, g_dbc);
    cudaGetSymbolAddress((void**)&pdt,  g_dt);
    cudaGetSymbolAddress((void**)&py,   g_y);

    // residual stream lives in d_out
    cudaMemcpyAsync(out, x, (size_t)NTOK * DIMD * sizeof(float),
                    cudaMemcpyDeviceToDevice);

    for (int blk = 0; blk < 4; blk++) {
        ln_kernel<<<NTOK / 8, 256>>>(out, lnw + blk * DIMD, lnb + blk * DIMD, ph);

        gemm128<1><<<dim3(8, 64), 256>>>(ph,
                                         inw + (size_t)blk * 2 * DIN * DIMD,
                                         inb + blk * 2 * DIN,
                                         pxz, NTOK, 2 * DIN, DIMD);

        conv_kernel<<<(NTOK * DIN) / 256, 256>>>(pxz,
                                                 cw + blk * DIN * 4,
                                                 cb + blk * DIN, pxc);

        gemm128<0><<<dim3(1, 64), 256>>>(pxc,
                                         xpw + (size_t)blk * DBCN * DIN,
                                         nullptr, pdbc, NTOK, DBCN, DIN);

        dtproj_kernel<<<NTOK, DIN>>>(pdbc,
                                     dtw + blk * DIN * DTRANK,
                                     dtb + blk * DIN, pdt);

        scan_kernel<<<dim3(8, 16), 128>>>(pxc, pdt, pdbc, pxz,
                                          Alog + (size_t)blk * DIN * DSTATE,
                                          Dp + blk * DIN, py);

        gemm128<2><<<dim3(2, 64), 256>>>(py,
                                         ow + (size_t)blk * DIMD * DIN,
                                         nullptr, out, NTOK, DIMD, DIN);
    }
}

// round 4
// speedup vs baseline: 1.3332x; 1.3332x over previous
#include <cuda_runtime.h>
#include <cuda.h>
#include <cstdint>

#define BB    16
#define LL    512
#define DIMD  256
#define DIN   512
#define DSTATE 16
#define DTRANK 16
#define NTOK  (BB*LL)   // 8192
#define DBCN  (DTRANK + 2*DSTATE)  // 48

// ------------- scratch (device globals: allocation-free) -------------
__device__ float g_h  [NTOK * DIMD];
__device__ float g_xz [NTOK * 2 * DIN];
__device__ float g_xc [NTOK * DIN];
__device__ float g_dbc[NTOK * DBCN];
__device__ float g_dt [NTOK * DIN];
__device__ float g_y  [NTOK * DIN];

// ===================== helpers =====================
__device__ __forceinline__ uint32_t smem_u32(const void* p) {
    uint32_t a;
    asm("{ .reg .u64 t; cvta.to.shared.u64 t, %1; cvt.u32.u64 %0, t; }" : "=r"(a) : "l"(p));
    return a;
}
__device__ __forceinline__ void cp_async16(uint32_t dst, const void* src) {
    asm volatile("cp.async.cg.shared.global [%0], [%1], 16;" :: "r"(dst), "l"(src));
}
// src-size form: bytes beyond src_sz (of the 16) are zero-filled
__device__ __forceinline__ void cp_async16z(uint32_t dst, const void* src, int src_sz) {
    asm volatile("cp.async.cg.shared.global [%0], [%1], 16, %2;" :: "r"(dst), "l"(src), "r"(src_sz));
}
#define CP_COMMIT() asm volatile("cp.async.commit_group;" ::: "memory")
#define CP_WAIT(n)  asm volatile("cp.async.wait_group %0;" :: "n"(n) : "memory")

// m16n8k8 tf32 mma (fp32 bits passed directly; HW truncates to tf32)
__device__ __forceinline__ void mma_tf32(float* c, const uint32_t* a, const uint32_t* b) {
    asm volatile(
        "mma.sync.aligned.m16n8k8.row.col.f32.tf32.tf32.f32 "
        "{%0,%1,%2,%3}, {%4,%5,%6,%7}, {%8,%9}, {%0,%1,%2,%3};"
        : "+f"(c[0]), "+f"(c[1]), "+f"(c[2]), "+f"(c[3])
        : "r"(a[0]), "r"(a[1]), "r"(a[2]), "r"(a[3]), "r"(b[0]), "r"(b[1]));
}

// ------------------------- LayerNorm -------------------------
__global__ void ln_kernel(const float* __restrict__ x,
                          const float* __restrict__ w,
                          const float* __restrict__ b,
                          float* __restrict__ h)
{
    int row  = blockIdx.x * 8 + (threadIdx.x >> 5);
    int lane = threadIdx.x & 31;
    const float* xr = x + (size_t)row * DIMD;
    float4 v0 = *(const float4*)(xr + lane * 8);
    float4 v1 = *(const float4*)(xr + lane * 8 + 4);
    float s  = v0.x+v0.y+v0.z+v0.w + v1.x+v1.y+v1.z+v1.w;
    float q  = v0.x*v0.x+v0.y*v0.y+v0.z*v0.z+v0.w*v0.w
             + v1.x*v1.x+v1.y*v1.y+v1.z*v1.z+v1.w*v1.w;
    #pragma unroll
    for (int o = 16; o; o >>= 1) {
        s += __shfl_xor_sync(0xffffffffu, s, o);
        q += __shfl_xor_sync(0xffffffffu, q, o);
    }
    float mu  = s * (1.f/DIMD);
    float var = q * (1.f/DIMD) - mu*mu;
    float rs  = rsqrtf(var + 1e-5f);
    float* hr = h + (size_t)row * DIMD;
    int c = lane * 8;
    float4 w0 = *(const float4*)(w + c),  w1 = *(const float4*)(w + c + 4);
    float4 b0 = *(const float4*)(b + c),  b1 = *(const float4*)(b + c + 4);
    float4 o0, o1;
    o0.x = (v0.x-mu)*rs*w0.x + b0.x;  o0.y = (v0.y-mu)*rs*w0.y + b0.y;
    o0.z = (v0.z-mu)*rs*w0.z + b0.z;  o0.w = (v0.w-mu)*rs*w0.w + b0.w;
    o1.x = (v1.x-mu)*rs*w1.x + b1.x;  o1.y = (v1.y-mu)*rs*w1.y + b1.y;
    o1.z = (v1.z-mu)*rs*w1.z + b1.z;  o1.w = (v1.w-mu)*rs*w1.w + b1.w;
    *(float4*)(hr + c)     = o0;
    *(float4*)(hr + c + 4) = o1;
}

// ========== tf32 mma.sync GEMM: C[M,N] = A[M,K] @ Bw[N,K]^T ==========
// MODE 0: plain   MODE 1: +bias[n]   MODE 2: C += acc (residual)
// CTA tile 128 x N_TILE, K-chunk 32, 8 warps, cp.async double buffer.
#define KCH 32
#define AST 36   // smem row stride in floats (32 data + 4 pad)

template<int N_TILE, int MODE>
__global__ __launch_bounds__(256)
void gemm_mma(const float* __restrict__ A, const float* __restrict__ Bw,
              const float* __restrict__ bias, float* __restrict__ C,
              int M, int N, int K)
{
    constexpr int WM = (N_TILE == 128) ? 2 : 4;       // warps along M
    constexpr int WN = 8 / WM;                        // warps along N
    constexpr int MSPAN = 128 / WM;                   // 64 or 32
    constexpr int NSPAN = N_TILE / WN;                // 32
    constexpr int MF = MSPAN / 16;                    // 4 or 2
    constexpr int NF = NSPAN / 8;                     // 4

    extern __shared__ float smf[];
    float* As = smf;                                  // 2 stages of 128*AST
    float* Bs = smf + 2 * 128 * AST;                  // 2 stages of N_TILE*AST

    const int tid  = threadIdx.x;
    const int lane = tid & 31;
    const int wid  = tid >> 5;
    const int g    = lane >> 2;       // group id (row within frag)
    const int tig  = lane & 3;        // thread in group
    const int row0 = blockIdx.y * 128;
    const int col0 = blockIdx.x * N_TILE;
    const int wm   = wid % WM;
    const int wn   = wid / WM;

    float acc[MF][NF][4];
    #pragma unroll
    for (int i = 0; i < MF; i++)
        #pragma unroll
        for (int j = 0; j < NF; j++)
            #pragma unroll
            for (int q = 0; q < 4; q++) acc[i][j][q] = 0.f;

    const int nch = K / KCH;
    const uint32_t a_s0 = smem_u32(As);
    const uint32_t b_s0 = smem_u32(Bs);

    // ---- prefetch lambda (stage st, chunk ch) ----
    auto prefetch = [&](int ch, int st) {
        int k0 = ch * KCH;
        uint32_t ab = a_s0 + (uint32_t)(st * 128 * AST) * 4u;
        #pragma unroll
        for (int i = 0; i < 4; i++) {
            int idx = tid + i * 256;       // 0..1023
            int r = idx >> 3, sgl = idx & 7;
            cp_async16(ab + (uint32_t)(r * AST + sgl * 4) * 4u,
                       A + (size_t)(row0 + r) * K + k0 + sgl * 4);
        }
        uint32_t bb = b_s0 + (uint32_t)(st * N_TILE * AST) * 4u;
        #pragma unroll
        for (int i = 0; i < N_TILE / 32; i++) {
            int idx = tid + i * 256;
            int r = idx >> 3, sgl = idx & 7;
            int sz = (col0 + r < N) ? 16 : 0;
            cp_async16z(bb + (uint32_t)(r * AST + sgl * 4) * 4u,
                        Bw + (size_t)(col0 + r) * K + k0 + sgl * 4, sz);
        }
    };

    prefetch(0, 0);
    CP_COMMIT();

    for (int ch = 0; ch < nch; ch++) {
        if (ch + 1 < nch) {
            prefetch(ch + 1, (ch + 1) & 1);
            CP_COMMIT();
            CP_WAIT(1);
        } else {
            CP_WAIT(0);
        }
        __syncthreads();

        int st = ch & 1;
        const float* Aw = As + st * 128 * AST + wm * MSPAN * AST;
        const float* Bww = Bs + st * N_TILE * AST + wn * NSPAN * AST;

        #pragma unroll
        for (int ks = 0; ks < 4; ks++) {
            int k0 = ks * 8;
            uint32_t a[MF][4];
            uint32_t b[NF][2];
            #pragma unroll
            for (int mf = 0; mf < MF; mf++) {
                const float* ap = Aw + (mf * 16 + g) * AST + k0 + tig;
                a[mf][0] = __float_as_uint(ap[0]);
                a[mf][2] = __float_as_uint(ap[4]);
                a[mf][1] = __float_as_uint(ap[8 * AST]);
                a[mf][3] = __float_as_uint(ap[8 * AST + 4]);
            }
            #pragma unroll
            for (int nf = 0; nf < NF; nf++) {
                const float* bp = Bww + (nf * 8 + g) * AST + k0 + tig;
                b[nf][0] = __float_as_uint(bp[0]);
                b[nf][1] = __float_as_uint(bp[4]);
            }
            #pragma unroll
            for (int mf = 0; mf < MF; mf++)
                #pragma unroll
                for (int nf = 0; nf < NF; nf++)
                    mma_tf32(acc[mf][nf], a[mf], b[nf]);
        }
        __syncthreads();
    }

    // ---- epilogue ----
    #pragma unroll
    for (int mf = 0; mf < MF; mf++) {
        #pragma unroll
        for (int nf = 0; nf < NF; nf++) {
            int mrow = row0 + wm * MSPAN + mf * 16 + g;
            int ncol = col0 + wn * NSPAN + nf * 8 + 2 * tig;
            if (ncol < N) {
                float2 v0 = make_float2(acc[mf][nf][0], acc[mf][nf][1]);
                float2 v1 = make_float2(acc[mf][nf][2], acc[mf][nf][3]);
                if (MODE == 1) {
                    float2 bb = *(const float2*)(bias + ncol);
                    v0.x += bb.x; v0.y += bb.y;
                    v1.x += bb.x; v1.y += bb.y;
                }
                float* c0 = C + (size_t)mrow * N + ncol;
                float* c1 = C + (size_t)(mrow + 8) * N + ncol;
                if (MODE == 2) {
                    float2 o0 = *(const float2*)c0;
                    float2 o1 = *(const float2*)c1;
                    v0.x += o0.x; v0.y += o0.y;
                    v1.x += o1.x; v1.y += o1.y;
                }
                *(float2*)c0 = v0;
                *(float2*)c1 = v1;
            }
        }
    }
}

// ------------------------- depthwise causal conv (k=4) + SiLU -------------------------
__global__ void conv_kernel(const float* __restrict__ xz,
                            const float* __restrict__ cw,
                            const float* __restrict__ cb,
                            float* __restrict__ xc)
{
    int idx = blockIdx.x * blockDim.x + threadIdx.x;
    if (idx >= NTOK * DIN) return;
    int d   = idx & (DIN - 1);
    int tok = idx >> 9;
    int l   = tok & (LL - 1);
    float s = cb[d];
    #pragma unroll
    for (int k = 0; k < 4; k++) {
        int ll = l - 3 + k;
        if (ll >= 0)
            s += cw[d*4 + k] * xz[(size_t)(tok - 3 + k) * 1024 + d];
    }
    float sg = 1.f / (1.f + __expf(-s));
    xc[idx] = s * sg;
}

// ------------------------- dt projection + softplus -------------------------
__global__ void dtproj_kernel(const float* __restrict__ dbc,
                              const float* __restrict__ dtw,
                              const float* __restrict__ dtb,
                              float* __restrict__ dt)
{
    int tok = blockIdx.x;
    int d   = threadIdx.x;
    const float* r = dbc + (size_t)tok * DBCN;
    float rv[16];
    #pragma unroll
    for (int i = 0; i < 16; i++) rv[i] = r[i];
    const float4* w4 = (const float4*)(dtw + d * 16);
    float4 w0 = w4[0], w1 = w4[1], w2 = w4[2], w3 = w4[3];
    float s = dtb[d];
    s += w0.x*rv[0]  + w0.y*rv[1]  + w0.z*rv[2]  + w0.w*rv[3];
    s += w1.x*rv[4]  + w1.y*rv[5]  + w1.z*rv[6]  + w1.w*rv[7];
    s += w2.x*rv[8]  + w2.y*rv[9]  + w2.z*rv[10] + w2.w*rv[11];
    s += w3.x*rv[12] + w3.y*rv[13] + w3.z*rv[14] + w3.w*rv[15];
    dt[(size_t)tok * DIN + d] = (s > 20.f) ? s : log1pf(__expf(s));
}

// ------------------------- selective scan -------------------------
__global__ __launch_bounds__(128)
void scan_kernel(const float* __restrict__ u,
                 const float* __restrict__ dt,
                 const float* __restrict__ dbc,
                 const float* __restrict__ xz,
                 const float* __restrict__ A_log,
                 const float* __restrict__ Dp,
                 float* __restrict__ y)
{
    const int tid   = threadIdx.x;
    const int lane  = tid & 31;
    const int warp  = tid >> 5;
    const int half  = lane >> 4;
    const int d     = blockIdx.x * 64 + warp * 16 + (lane & 15);
    const int bbase = blockIdx.y * LL;

    float A[8];
    #pragma unroll
    for (int i = 0; i < 8; i++)
        A[i] = -__expf(A_log[d * DSTATE + half * 8 + i]);
    const float Dd = Dp[d];

    float h[8];
    #pragma unroll
    for (int i = 0; i < 8; i++) h[i] = 0.f;

    __shared__ float sB[8][16];
    __shared__ float sC[8][16];

    for (int t0 = 0; t0 < LL; t0 += 8) {
        __syncthreads();
        #pragma unroll
        for (int i = tid; i < 256; i += 128) {
            int step = i >> 5, idx = i & 31;
            float v = dbc[(size_t)(bbase + t0 + step) * DBCN + DTRANK + idx];
            if (idx < 16) sB[step][idx] = v;
            else          sC[step][idx - 16] = v;
        }
        __syncthreads();
        #pragma unroll
        for (int s = 0; s < 8; s++) {
            int tok = bbase + t0 + s;
            float dtv = dt[(size_t)tok * DIN + d];
            float uv  = u [(size_t)tok * DIN + d];
            float du  = dtv * uv;
            float yp  = 0.f;
            #pragma unroll
            for (int i = 0; i < 8; i++) {
                float dA = __expf(dtv * A[i]);
                float Bv = sB[s][half * 8 + i];
                h[i] = dA * h[i] + du * Bv;
                yp += h[i] * sC[s][half * 8 + i];
            }
            float ytot = yp + __shfl_xor_sync(0xffffffffu, yp, 16);
            if (half == 0) {
                float zv = xz[(size_t)tok * 1024 + DIN + d];
                float sz = zv / (1.f + __expf(-zv));
                y[(size_t)tok * DIN + d] = (ytot + uv * Dd) * sz;
            }
        }
    }
}

// ------------------------- host -------------------------
extern "C" void kernel_launch(void* const* d_in, const int* in_sizes, int n_in,
                              void* d_out, int out_size)
{
    const float* x    = (const float*)d_in[0];
    const float* lnw  = (const float*)d_in[1];
    const float* lnb  = (const float*)d_in[2];
    const float* inw  = (const float*)d_in[3];
    const float* inb  = (const float*)d_in[4];
    const float* cw   = (const float*)d_in[5];
    const float* cb   = (const float*)d_in[6];
    const float* xpw  = (const float*)d_in[7];
    const float* dtw  = (const float*)d_in[8];
    const float* dtb  = (const float*)d_in[9];
    const float* Alog = (const float*)d_in[10];
    const float* Dp   = (const float*)d_in[11];
    const float* ow   = (const float*)d_in[12];
    float* out = (float*)d_out;

    float *ph, *pxz, *pxc, *pdbc, *pdt, *py;
    cudaGetSymbolAddress((void**)&ph,   g_h);
    cudaGetSymbolAddress((void**)&pxz,  g_xz);
    cudaGetSymbolAddress((void**)&pxc,  g_xc);
    cudaGetSymbolAddress((void**)&pdbc, g_dbc);
    cudaGetSymbolAddress((void**)&pdt,  g_dt);
    cudaGetSymbolAddress((void**)&py,   g_y);

    const int SM128 = (2 * 128 * AST + 2 * 128 * AST) * 4;  // 73728
    const int SM64  = (2 * 128 * AST + 2 * 64  * AST) * 4;  // 55296
    cudaFuncSetAttribute(gemm_mma<128,1>, cudaFuncAttributeMaxDynamicSharedMemorySize, SM128);
    cudaFuncSetAttribute(gemm_mma<128,2>, cudaFuncAttributeMaxDynamicSharedMemorySize, SM128);
    cudaFuncSetAttribute(gemm_mma<64,0>,  cudaFuncAttributeMaxDynamicSharedMemorySize, SM64);

    cudaMemcpyAsync(out, x, (size_t)NTOK * DIMD * sizeof(float),
                    cudaMemcpyDeviceToDevice);

    for (int blk = 0; blk < 4; blk++) {
        ln_kernel<<<NTOK / 8, 256>>>(out, lnw + blk * DIMD, lnb + blk * DIMD, ph);

        gemm_mma<128,1><<<dim3(8, 64), 256, SM128>>>(ph,
                inw + (size_t)blk * 2 * DIN * DIMD,
                inb + blk * 2 * DIN,
                pxz, NTOK, 2 * DIN, DIMD);

        conv_kernel<<<(NTOK * DIN) / 256, 256>>>(pxz,
                cw + blk * DIN * 4, cb + blk * DIN, pxc);

        gemm_mma<64,0><<<dim3(1, 64), 256, SM64>>>(pxc,
                xpw + (size_t)blk * DBCN * DIN,
                nullptr, pdbc, NTOK, DBCN, DIN);

        dtproj_kernel<<<NTOK, DIN>>>(pdbc,
                dtw + blk * DIN * DTRANK, dtb + blk * DIN, pdt);

        scan_kernel<<<dim3(8, 16), 128>>>(pxc, pdt, pdbc, pxz,
                Alog + (size_t)blk * DIN * DSTATE, Dp + blk * DIN, py);

        gemm_mma<128,2><<<dim3(2, 64), 256, SM128>>>(py,
                ow + (size_t)blk * DIMD * DIN,
                nullptr, out, NTOK, DIMD, DIN);
    }
}

// round 5
// speedup vs baseline: 1.7800x; 1.3351x over previous
#include <cuda_runtime.h>
#include <cuda.h>
#include <cstdint>

#define BB    16
#define LL    512
#define DIMD  256
#define DIN   512
#define DSTATE 16
#define DTRANK 16
#define NTOK  (BB*LL)   // 8192
#define DBCN  (DTRANK + 2*DSTATE)  // 48
#define NCHUNK 8
#define CLEN   64

// ------------- scratch (device globals: allocation-free) -------------
__device__ float g_h   [NTOK * DIMD];
__device__ float g_xz  [NTOK * 2 * DIN];
__device__ float g_xc  [NTOK * DIN];
__device__ float g_dbc [NTOK * DBCN];
__device__ float g_dt  [NTOK * DIN];
__device__ float g_y   [NTOK * DIN];
__device__ float g_cum [NTOK * DIN];
__device__ float g_hfin[BB * NCHUNK * DIN * DSTATE];   // 4 MB
__device__ float g_A   [DIN * DSTATE];

// ===================== helpers =====================
__device__ __forceinline__ uint32_t smem_u32(const void* p) {
    uint32_t a;
    asm("{ .reg .u64 t; cvta.to.shared.u64 t, %1; cvt.u32.u64 %0, t; }" : "=r"(a) : "l"(p));
    return a;
}
__device__ __forceinline__ void cp_async16(uint32_t dst, const void* src) {
    asm volatile("cp.async.cg.shared.global [%0], [%1], 16;" :: "r"(dst), "l"(src));
}
__device__ __forceinline__ void cp_async16z(uint32_t dst, const void* src, int src_sz) {
    asm volatile("cp.async.cg.shared.global [%0], [%1], 16, %2;" :: "r"(dst), "l"(src), "r"(src_sz));
}
#define CP_COMMIT() asm volatile("cp.async.commit_group;" ::: "memory")
#define CP_WAIT(n)  asm volatile("cp.async.wait_group %0;" :: "n"(n) : "memory")

__device__ __forceinline__ void mma_tf32(float* c, const uint32_t* a, const uint32_t* b) {
    asm volatile(
        "mma.sync.aligned.m16n8k8.row.col.f32.tf32.tf32.f32 "
        "{%0,%1,%2,%3}, {%4,%5,%6,%7}, {%8,%9}, {%0,%1,%2,%3};"
        : "+f"(c[0]), "+f"(c[1]), "+f"(c[2]), "+f"(c[3])
        : "r"(a[0]), "r"(a[1]), "r"(a[2]), "r"(a[3]), "r"(b[0]), "r"(b[1]));
}

// ------------------------- LayerNorm -------------------------
__global__ void ln_kernel(const float* __restrict__ x,
                          const float* __restrict__ w,
                          const float* __restrict__ b,
                          float* __restrict__ h)
{
    int row  = blockIdx.x * 8 + (threadIdx.x >> 5);
    int lane = threadIdx.x & 31;
    const float* xr = x + (size_t)row * DIMD;
    float4 v0 = *(const float4*)(xr + lane * 8);
    float4 v1 = *(const float4*)(xr + lane * 8 + 4);
    float s  = v0.x+v0.y+v0.z+v0.w + v1.x+v1.y+v1.z+v1.w;
    float q  = v0.x*v0.x+v0.y*v0.y+v0.z*v0.z+v0.w*v0.w
             + v1.x*v1.x+v1.y*v1.y+v1.z*v1.z+v1.w*v1.w;
    #pragma unroll
    for (int o = 16; o; o >>= 1) {
        s += __shfl_xor_sync(0xffffffffu, s, o);
        q += __shfl_xor_sync(0xffffffffu, q, o);
    }
    float mu  = s * (1.f/DIMD);
    float var = q * (1.f/DIMD) - mu*mu;
    float rs  = rsqrtf(var + 1e-5f);
    float* hr = h + (size_t)row * DIMD;
    int c = lane * 8;
    float4 w0 = *(const float4*)(w + c),  w1 = *(const float4*)(w + c + 4);
    float4 b0 = *(const float4*)(b + c),  b1 = *(const float4*)(b + c + 4);
    float4 o0, o1;
    o0.x = (v0.x-mu)*rs*w0.x + b0.x;  o0.y = (v0.y-mu)*rs*w0.y + b0.y;
    o0.z = (v0.z-mu)*rs*w0.z + b0.z;  o0.w = (v0.w-mu)*rs*w0.w + b0.w;
    o1.x = (v1.x-mu)*rs*w1.x + b1.x;  o1.y = (v1.y-mu)*rs*w1.y + b1.y;
    o1.z = (v1.z-mu)*rs*w1.z + b1.z;  o1.w = (v1.w-mu)*rs*w1.w + b1.w;
    *(float4*)(hr + c)     = o0;
    *(float4*)(hr + c + 4) = o1;
}

// ========== tf32 mma.sync GEMM: C[M,N] = A[M,K] @ Bw[N,K]^T ==========
#define KCH 32
#define AST 36

template<int N_TILE, int MODE>
__global__ __launch_bounds__(256)
void gemm_mma(const float* __restrict__ A, const float* __restrict__ Bw,
              const float* __restrict__ bias, float* __restrict__ C,
              int M, int N, int K)
{
    constexpr int WM = (N_TILE == 128) ? 2 : 4;
    constexpr int WN = 8 / WM;
    constexpr int MSPAN = 128 / WM;
    constexpr int NSPAN = N_TILE / WN;
    constexpr int MF = MSPAN / 16;
    constexpr int NF = NSPAN / 8;

    extern __shared__ float smf[];
    float* As = smf;
    float* Bs = smf + 2 * 128 * AST;

    const int tid  = threadIdx.x;
    const int lane = tid & 31;
    const int wid  = tid >> 5;
    const int g    = lane >> 2;
    const int tig  = lane & 3;
    const int row0 = blockIdx.y * 128;
    const int col0 = blockIdx.x * N_TILE;
    const int wm   = wid % WM;
    const int wn   = wid / WM;

    float acc[MF][NF][4];
    #pragma unroll
    for (int i = 0; i < MF; i++)
        #pragma unroll
        for (int j = 0; j < NF; j++)
            #pragma unroll
            for (int q = 0; q < 4; q++) acc[i][j][q] = 0.f;

    const int nch = K / KCH;
    const uint32_t a_s0 = smem_u32(As);
    const uint32_t b_s0 = smem_u32(Bs);

    auto prefetch = [&](int ch, int st) {
        int k0 = ch * KCH;
        uint32_t ab = a_s0 + (uint32_t)(st * 128 * AST) * 4u;
        #pragma unroll
        for (int i = 0; i < 4; i++) {
            int idx = tid + i * 256;
            int r = idx >> 3, sgl = idx & 7;
            cp_async16(ab + (uint32_t)(r * AST + sgl * 4) * 4u,
                       A + (size_t)(row0 + r) * K + k0 + sgl * 4);
        }
        uint32_t bb = b_s0 + (uint32_t)(st * N_TILE * AST) * 4u;
        #pragma unroll
        for (int i = 0; i < N_TILE / 32; i++) {
            int idx = tid + i * 256;
            int r = idx >> 3, sgl = idx & 7;
            int sz = (col0 + r < N) ? 16 : 0;
            cp_async16z(bb + (uint32_t)(r * AST + sgl * 4) * 4u,
                        Bw + (size_t)(col0 + r) * K + k0 + sgl * 4, sz);
        }
    };

    prefetch(0, 0);
    CP_COMMIT();

    for (int ch = 0; ch < nch; ch++) {
        if (ch + 1 < nch) {
            prefetch(ch + 1, (ch + 1) & 1);
            CP_COMMIT();
            CP_WAIT(1);
        } else {
            CP_WAIT(0);
        }
        __syncthreads();

        int st = ch & 1;
        const float* Aw  = As + st * 128 * AST + wm * MSPAN * AST;
        const float* Bww = Bs + st * N_TILE * AST + wn * NSPAN * AST;

        #pragma unroll
        for (int ks = 0; ks < 4; ks++) {
            int k0 = ks * 8;
            uint32_t a[MF][4];
            uint32_t b[NF][2];
            #pragma unroll
            for (int mf = 0; mf < MF; mf++) {
                const float* ap = Aw + (mf * 16 + g) * AST + k0 + tig;
                a[mf][0] = __float_as_uint(ap[0]);
                a[mf][2] = __float_as_uint(ap[4]);
                a[mf][1] = __float_as_uint(ap[8 * AST]);
                a[mf][3] = __float_as_uint(ap[8 * AST + 4]);
            }
            #pragma unroll
            for (int nf = 0; nf < NF; nf++) {
                const float* bp = Bww + (nf * 8 + g) * AST + k0 + tig;
                b[nf][0] = __float_as_uint(bp[0]);
                b[nf][1] = __float_as_uint(bp[4]);
            }
            #pragma unroll
            for (int mf = 0; mf < MF; mf++)
                #pragma unroll
                for (int nf = 0; nf < NF; nf++)
                    mma_tf32(acc[mf][nf], a[mf], b[nf]);
        }
        __syncthreads();
    }

    #pragma unroll
    for (int mf = 0; mf < MF; mf++) {
        #pragma unroll
        for (int nf = 0; nf < NF; nf++) {
            int mrow = row0 + wm * MSPAN + mf * 16 + g;
            int ncol = col0 + wn * NSPAN + nf * 8 + 2 * tig;
            if (ncol < N) {
                float2 v0 = make_float2(acc[mf][nf][0], acc[mf][nf][1]);
                float2 v1 = make_float2(acc[mf][nf][2], acc[mf][nf][3]);
                if (MODE == 1) {
                    float2 bb = *(const float2*)(bias + ncol);
                    v0.x += bb.x; v0.y += bb.y;
                    v1.x += bb.x; v1.y += bb.y;
                }
                float* c0 = C + (size_t)mrow * N + ncol;
                float* c1 = C + (size_t)(mrow + 8) * N + ncol;
                if (MODE == 2) {
                    float2 o0 = *(const float2*)c0;
                    float2 o1 = *(const float2*)c1;
                    v0.x += o0.x; v0.y += o0.y;
                    v1.x += o1.x; v1.y += o1.y;
                }
                *(float2*)c0 = v0;
                *(float2*)c1 = v1;
            }
        }
    }
}

// ------------------------- depthwise causal conv (k=4) + SiLU -------------------------
__global__ void conv_kernel(const float* __restrict__ xz,
                            const float* __restrict__ cw,
                            const float* __restrict__ cb,
                            float* __restrict__ xc)
{
    int idx = blockIdx.x * blockDim.x + threadIdx.x;
    if (idx >= NTOK * DIN) return;
    int d   = idx & (DIN - 1);
    int tok = idx >> 9;
    int l   = tok & (LL - 1);
    float s = cb[d];
    #pragma unroll
    for (int k = 0; k < 4; k++) {
        int ll = l - 3 + k;
        if (ll >= 0)
            s += cw[d*4 + k] * xz[(size_t)(tok - 3 + k) * 1024 + d];
    }
    float sg = 1.f / (1.f + __expf(-s));
    xc[idx] = s * sg;
}

// ------------------------- dt projection + softplus -------------------------
__global__ void dtproj_kernel(const float* __restrict__ dbc,
                              const float* __restrict__ dtw,
                              const float* __restrict__ dtb,
                              float* __restrict__ dt)
{
    int tok = blockIdx.x;
    int d   = threadIdx.x;
    const float* r = dbc + (size_t)tok * DBCN;
    float rv[16];
    #pragma unroll
    for (int i = 0; i < 16; i++) rv[i] = r[i];
    const float4* w4 = (const float4*)(dtw + d * 16);
    float4 w0 = w4[0], w1 = w4[1], w2 = w4[2], w3 = w4[3];
    float s = dtb[d];
    s += w0.x*rv[0]  + w0.y*rv[1]  + w0.z*rv[2]  + w0.w*rv[3];
    s += w1.x*rv[4]  + w1.y*rv[5]  + w1.z*rv[6]  + w1.w*rv[7];
    s += w2.x*rv[8]  + w2.y*rv[9]  + w2.z*rv[10] + w2.w*rv[11];
    s += w3.x*rv[12] + w3.y*rv[13] + w3.z*rv[14] + w3.w*rv[15];
    dt[(size_t)tok * DIN + d] = (s > 20.f) ? s : log1pf(__expf(s));
}

// ------------------------- A precompute -------------------------
__global__ void prepA_kernel(const float* __restrict__ A_log, float* __restrict__ Ax)
{
    int i = blockIdx.x * 256 + threadIdx.x;
    Ax[i] = -__expf(A_log[i]);
}

// ------------------------- scan phase 1: local chunk scans -------------------------
// grid (8 ch-groups, 16 batches, 8 time-chunks), 128 threads.
// thread = (channel, 8-state half); chunk scan with h0 = 0, no gating.
__global__ __launch_bounds__(128)
void scan_local(const float* __restrict__ u,
                const float* __restrict__ dt,
                const float* __restrict__ dbc,
                const float* __restrict__ Ax,
                float* __restrict__ yloc,
                float* __restrict__ cum,
                float* __restrict__ hfin)
{
    const int tid  = threadIdx.x;
    const int lane = tid & 31;
    const int warp = tid >> 5;
    const int half = lane >> 4;
    const int d    = blockIdx.x * 64 + warp * 16 + (lane & 15);
    const int b    = blockIdx.y;
    const int c    = blockIdx.z;
    const int tok0 = b * LL + c * CLEN;

    float A[8];
    #pragma unroll
    for (int i = 0; i < 8; i++) A[i] = Ax[d * DSTATE + half * 8 + i];

    float h[8];
    #pragma unroll
    for (int i = 0; i < 8; i++) h[i] = 0.f;
    float cm = 0.f;

    __shared__ float sB[8][16];
    __shared__ float sC[8][16];

    for (int t0 = 0; t0 < CLEN; t0 += 8) {
        __syncthreads();
        #pragma unroll
        for (int i = tid; i < 256; i += 128) {
            int step = i >> 5, idx = i & 31;
            float v = dbc[(size_t)(tok0 + t0 + step) * DBCN + DTRANK + idx];
            if (idx < 16) sB[step][idx] = v;
            else          sC[step][idx - 16] = v;
        }
        __syncthreads();
        // batched loads for 8 steps (deep MLP)
        float dtv[8], uv[8];
        #pragma unroll
        for (int s = 0; s < 8; s++) {
            int tok = tok0 + t0 + s;
            dtv[s] = dt[(size_t)tok * DIN + d];
            uv[s]  = u [(size_t)tok * DIN + d];
        }
        #pragma unroll
        for (int s = 0; s < 8; s++) {
            int tok = tok0 + t0 + s;
            cm += dtv[s];
            float du = dtv[s] * uv[s];
            float yp = 0.f;
            #pragma unroll
            for (int i = 0; i < 8; i++) {
                float dA = __expf(dtv[s] * A[i]);
                h[i] = dA * h[i] + du * sB[s][half * 8 + i];
                yp += h[i] * sC[s][half * 8 + i];
            }
            float yt = yp + __shfl_xor_sync(0xffffffffu, yp, 16);
            if (half == 0) {
                yloc[(size_t)tok * DIN + d] = yt;
                cum [(size_t)tok * DIN + d] = cm;
            }
        }
    }
    size_t base = ((size_t)(b * NCHUNK + c) * DIN + d) * DSTATE + half * 8;
    #pragma unroll
    for (int i = 0; i < 8; i++) hfin[base + i] = h[i];
}

// ------------------------- scan phase 2: chunk combine -------------------------
// 131072 threads; each owns one (batch, channel, state). hfin -> h_in in place.
__global__ void scan_combine(const float* __restrict__ cum,
                             const float* __restrict__ Ax,
                             float* __restrict__ hfin)
{
    int idx = blockIdx.x * 256 + threadIdx.x;
    int n  = idx & 15;
    int ch = (idx >> 4) & (DIN - 1);
    int b  = idx >> 13;
    float An = Ax[ch * DSTATE + n];
    float carry = 0.f;
    #pragma unroll
    for (int c = 0; c < NCHUNK; c++) {
        float S = cum[(size_t)(b * LL + c * CLEN + CLEN - 1) * DIN + ch];
        size_t o = ((size_t)(b * NCHUNK + c) * DIN + ch) * DSTATE + n;
        float F = hfin[o];
        hfin[o] = carry;
        carry = __expf(An * S) * carry + F;
    }
}

// ------------------------- scan phase 3: fixup + gating -------------------------
// one thread per (token, channel). y = (y_loc + C·(e^{A cum} h_in) + u*D) * silu(z)
__global__ __launch_bounds__(256)
void scan_fixup(const float* __restrict__ u,
                const float* __restrict__ cum,
                const float* __restrict__ dbc,
                const float* __restrict__ xz,
                const float* __restrict__ Ax,
                const float* __restrict__ Dp,
                const float* __restrict__ hfin,
                float* __restrict__ y)
{
    int idx = blockIdx.x * 256 + threadIdx.x;
    int ch  = idx & (DIN - 1);
    int tok = idx >> 9;
    int b   = tok >> 9;
    int l   = tok & (LL - 1);
    int c   = l >> 6;

    float cm = cum[idx];
    const float* Ar = Ax + ch * DSTATE;
    const float* Cr = dbc + (size_t)tok * DBCN + DTRANK + DSTATE;
    const float* hr = hfin + ((size_t)(b * NCHUNK + c) * DIN + ch) * DSTATE;

    float corr = 0.f;
    #pragma unroll
    for (int n = 0; n < 16; n++)
        corr += Cr[n] * hr[n] * __expf(Ar[n] * cm);

    float uv = u[idx];
    float zv = xz[(size_t)tok * 1024 + DIN + ch];
    float sz = zv / (1.f + __expf(-zv));
    y[idx] = (y[idx] + corr + uv * Dp[ch]) * sz;
}

// ------------------------- host -------------------------
extern "C" void kernel_launch(void* const* d_in, const int* in_sizes, int n_in,
                              void* d_out, int out_size)
{
    const float* x    = (const float*)d_in[0];
    const float* lnw  = (const float*)d_in[1];
    const float* lnb  = (const float*)d_in[2];
    const float* inw  = (const float*)d_in[3];
    const float* inb  = (const float*)d_in[4];
    const float* cw   = (const float*)d_in[5];
    const float* cb   = (const float*)d_in[6];
    const float* xpw  = (const float*)d_in[7];
    const float* dtw  = (const float*)d_in[8];
    const float* dtb  = (const float*)d_in[9];
    const float* Alog = (const float*)d_in[10];
    const float* Dp   = (const float*)d_in[11];
    const float* ow   = (const float*)d_in[12];
    float* out = (float*)d_out;

    float *ph, *pxz, *pxc, *pdbc, *pdt, *py, *pcum, *phf, *pA;
    cudaGetSymbolAddress((void**)&ph,   g_h);
    cudaGetSymbolAddress((void**)&pxz,  g_xz);
    cudaGetSymbolAddress((void**)&pxc,  g_xc);
    cudaGetSymbolAddress((void**)&pdbc, g_dbc);
    cudaGetSymbolAddress((void**)&pdt,  g_dt);
    cudaGetSymbolAddress((void**)&py,   g_y);
    cudaGetSymbolAddress((void**)&pcum, g_cum);
    cudaGetSymbolAddress((void**)&phf,  g_hfin);
    cudaGetSymbolAddress((void**)&pA,   g_A);

    const int SM128 = (2 * 128 * AST + 2 * 128 * AST) * 4;
    const int SM64  = (2 * 128 * AST + 2 * 64  * AST) * 4;
    cudaFuncSetAttribute(gemm_mma<128,1>, cudaFuncAttributeMaxDynamicSharedMemorySize, SM128);
    cudaFuncSetAttribute(gemm_mma<128,2>, cudaFuncAttributeMaxDynamicSharedMemorySize, SM128);
    cudaFuncSetAttribute(gemm_mma<64,0>,  cudaFuncAttributeMaxDynamicSharedMemorySize, SM64);

    cudaMemcpyAsync(out, x, (size_t)NTOK * DIMD * sizeof(float),
                    cudaMemcpyDeviceToDevice);

    for (int blk = 0; blk < 4; blk++) {
        ln_kernel<<<NTOK / 8, 256>>>(out, lnw + blk * DIMD, lnb + blk * DIMD, ph);

        gemm_mma<128,1><<<dim3(8, 64), 256, SM128>>>(ph,
                inw + (size_t)blk * 2 * DIN * DIMD,
                inb + blk * 2 * DIN,
                pxz, NTOK, 2 * DIN, DIMD);

        conv_kernel<<<(NTOK * DIN) / 256, 256>>>(pxz,
                cw + blk * DIN * 4, cb + blk * DIN, pxc);

        gemm_mma<64,0><<<dim3(1, 64), 256, SM64>>>(pxc,
                xpw + (size_t)blk * DBCN * DIN,
                nullptr, pdbc, NTOK, DBCN, DIN);

        dtproj_kernel<<<NTOK, DIN>>>(pdbc,
                dtw + blk * DIN * DTRANK, dtb + blk * DIN, pdt);

        prepA_kernel<<<DIN * DSTATE / 256, 256>>>(Alog + (size_t)blk * DIN * DSTATE, pA);

        scan_local<<<dim3(8, 16, 8), 128>>>(pxc, pdt, pdbc, pA, py, pcum, phf);

        scan_combine<<<BB * DIN * DSTATE / 256, 256>>>(pcum, pA, phf);

        scan_fixup<<<(NTOK * DIN) / 256, 256>>>(pxc, pcum, pdbc, pxz, pA,
                Dp + blk * DIN, phf, py);

        gemm_mma<128,2><<<dim3(2, 64), 256, SM128>>>(py,
                ow + (size_t)blk * DIMD * DIN,
                nullptr, out, NTOK, DIMD, DIN);
    }
}